// round 1
// baseline (speedup 1.0000x reference)
#include <cuda_runtime.h>

#define EPSBN 1e-5f

#define B_  16384
#define D0  784
#define D1  3072
#define D2  1536
#define D3  768
#define D4  10
#define NW1 (D1/32)   // 96 words per row of layer-2 input bits
#define NW2 (D2/32)   // 48 words per row of layer-3 input bits

// ------------------------- static device scratch -------------------------
__device__ float        d_w1s[D0*D1];       // sign(w1) transposed [K][N], float +-1 (or 0)
__device__ unsigned     d_w2bits[D2*NW1];
__device__ unsigned     d_w3bits[D3*NW2];
__device__ unsigned     d_a1bits[B_*NW1];   // sign(bn1) bits
__device__ unsigned     d_a2bits[B_*NW2];   // sign(bn2) bits
__device__ float        d_h3c[B_*D3];       // clip(bn3)
__device__ float        d_thr1[D1], d_sg1[D1];
__device__ float        d_thr2[D2], d_sg2[D2];
__device__ float        d_s3[D3],   d_o3[D3];

// ------------------------- f32x2 helpers (sm_103a FFMA2 path) -------------
__device__ __forceinline__ unsigned long long pack2dup(float a) {
    unsigned long long r;
    asm("mov.b64 %0, {%1, %2};" : "=l"(r) : "f"(a), "f"(a));
    return r;
}
__device__ __forceinline__ void fma2(unsigned long long& d, unsigned long long a, unsigned long long b) {
    asm("fma.rn.f32x2 %0, %1, %2, %0;" : "+l"(d) : "l"(a), "l"(b));
}
__device__ __forceinline__ void unpack2(unsigned long long v, float& x, float& y) {
    asm("mov.b64 {%0, %1}, %2;" : "=f"(x), "=f"(y) : "l"(v));
}

// ------------------------- prep kernels ----------------------------------
__global__ void prep_w1s(const float* __restrict__ w1) {
    int idx = blockIdx.x * 256 + threadIdx.x;
    if (idx >= D1 * D0) return;
    int n = idx / D0, k = idx % D0;
    float w = w1[idx];
    d_w1s[k * D1 + n] = (w > 0.f) ? 1.f : (w < 0.f ? -1.f : 0.f);
}

__global__ void prep_bits(const float* __restrict__ w2, const float* __restrict__ w3) {
    int idx = blockIdx.x * 256 + threadIdx.x;
    if (idx < D2 * NW1) {
        int j = idx / NW1, w = idx % NW1;
        const float* p = w2 + j * D1 + w * 32;
        unsigned word = 0;
        #pragma unroll
        for (int b = 0; b < 32; b++) word |= (p[b] > 0.f) ? (1u << b) : 0u;
        d_w2bits[idx] = word;
    }
    if (idx < D3 * NW2) {
        int j = idx / NW2, w = idx % NW2;
        const float* p = w3 + j * D2 + w * 32;
        unsigned word = 0;
        #pragma unroll
        for (int b = 0; b < 32; b++) word |= (p[b] > 0.f) ? (1u << b) : 0u;
        d_w3bits[idx] = word;
    }
}

__global__ void prep_params(
    const float* __restrict__ b1, const float* __restrict__ g1, const float* __restrict__ be1,
    const float* __restrict__ m1, const float* __restrict__ v1,
    const float* __restrict__ b2, const float* __restrict__ g2, const float* __restrict__ be2,
    const float* __restrict__ m2, const float* __restrict__ v2,
    const float* __restrict__ b3, const float* __restrict__ g3, const float* __restrict__ be3,
    const float* __restrict__ m3, const float* __restrict__ v3)
{
    int j = blockIdx.x * 256 + threadIdx.x;
    if (j < D1) {
        float g = g1[j];
        d_thr1[j] = m1[j] - be1[j] * sqrtf(v1[j] + EPSBN) / g - b1[j];
        d_sg1[j]  = (g > 0.f) ? 1.f : -1.f;
    }
    if (j < D2) {
        float g = g2[j];
        d_thr2[j] = m2[j] - be2[j] * sqrtf(v2[j] + EPSBN) / g - b2[j];
        d_sg2[j]  = (g > 0.f) ? 1.f : -1.f;
    }
    if (j < D3) {
        float g = g3[j];
        float s = g / sqrtf(v3[j] + EPSBN);
        d_s3[j] = s;
        d_o3[j] = (b3[j] - m3[j]) * s + be3[j];
    }
}

// ------------------------- fc1: fp32 GEMM + BN-threshold + bitpack -------
// C[16384,3072] = x[16384,784] * w1s[784,3072]; epilogue: bit = sg*(dot-thr)>0
__global__ __launch_bounds__(256, 2) void gemm1_kernel(const float* __restrict__ x) {
    __shared__ __align__(16) float sm[16 * 132 + 16 * 128];   // As | Bs, 16640 B
    float (*As)[132] = (float(*)[132])sm;                      // [k][m], padded
    float (*Bs)[128] = (float(*)[128])(sm + 16 * 132);         // [k][n]
    unsigned char* flags = (unsigned char*)sm;                 // 16384 B, aliases As/Bs

    int tid = threadIdx.x;
    int tx = tid & 15, ty = tid >> 4;
    int m0 = blockIdx.y * 128, n0 = blockIdx.x * 128;

    unsigned long long acc[8][4];
    #pragma unroll
    for (int r = 0; r < 8; r++)
        #pragma unroll
        for (int c = 0; c < 4; c++) acc[r][c] = 0ull;

    int lr = tid >> 2, lq = tid & 3;       // A loader: row, k-quad
    int bk = tid >> 5, bq = tid & 31;      // B loader: k-row, n-quad
    const float* xA0 = x + (size_t)(m0 + lr)      * D0 + lq * 4;
    const float* xA1 = x + (size_t)(m0 + lr + 64) * D0 + lq * 4;
    const float* pB0 = d_w1s + (size_t)bk       * D1 + n0 + bq * 4;
    const float* pB1 = d_w1s + (size_t)(bk + 8) * D1 + n0 + bq * 4;

    for (int kt = 0; kt < D0; kt += 16) {
        float4 av0 = *(const float4*)(xA0 + kt);
        float4 av1 = *(const float4*)(xA1 + kt);
        float4 bv0 = *(const float4*)(pB0 + (size_t)kt * D1);
        float4 bv1 = *(const float4*)(pB1 + (size_t)kt * D1);
        As[lq * 4 + 0][lr] = av0.x; As[lq * 4 + 1][lr] = av0.y;
        As[lq * 4 + 2][lr] = av0.z; As[lq * 4 + 3][lr] = av0.w;
        As[lq * 4 + 0][lr + 64] = av1.x; As[lq * 4 + 1][lr + 64] = av1.y;
        As[lq * 4 + 2][lr + 64] = av1.z; As[lq * 4 + 3][lr + 64] = av1.w;
        *(float4*)&Bs[bk][bq * 4]     = bv0;
        *(float4*)&Bs[bk + 8][bq * 4] = bv1;
        __syncthreads();

        #pragma unroll
        for (int kk = 0; kk < 16; kk++) {
            float4 a0 = *(const float4*)&As[kk][ty * 8];
            float4 a1 = *(const float4*)&As[kk][ty * 8 + 4];
            double2 q0 = *(const double2*)&Bs[kk][tx * 8];
            double2 q1 = *(const double2*)&Bs[kk][tx * 8 + 4];
            unsigned long long b0 = __double_as_longlong(q0.x);
            unsigned long long b1 = __double_as_longlong(q0.y);
            unsigned long long b2 = __double_as_longlong(q1.x);
            unsigned long long b3 = __double_as_longlong(q1.y);
            float aa[8] = {a0.x, a0.y, a0.z, a0.w, a1.x, a1.y, a1.z, a1.w};
            #pragma unroll
            for (int r = 0; r < 8; r++) {
                unsigned long long ar = pack2dup(aa[r]);
                fma2(acc[r][0], ar, b0);
                fma2(acc[r][1], ar, b1);
                fma2(acc[r][2], ar, b2);
                fma2(acc[r][3], ar, b3);
            }
        }
        __syncthreads();
    }

    // Epilogue: threshold compare -> flags in smem
    float thr[8], sg[8];
    #pragma unroll
    for (int c = 0; c < 8; c++) {
        int n = n0 + tx * 8 + c;
        thr[c] = d_thr1[n];
        sg[c]  = d_sg1[n];
    }
    #pragma unroll
    for (int r = 0; r < 8; r++) {
        #pragma unroll
        for (int c2 = 0; c2 < 4; c2++) {
            float lo, hi;
            unpack2(acc[r][c2], lo, hi);
            int c = c2 * 2;
            flags[(ty * 8 + r) * 128 + tx * 8 + c]     = (sg[c]     * (lo - thr[c])     > 0.f) ? 1 : 0;
            flags[(ty * 8 + r) * 128 + tx * 8 + c + 1] = (sg[c + 1] * (hi - thr[c + 1]) > 0.f) ? 1 : 0;
        }
    }
    __syncthreads();

    // Pack 128x128 flags -> 128 rows x 4 words
    #pragma unroll
    for (int t = 0; t < 2; t++) {
        int task = tid * 2 + t;
        int row = task >> 2, wq = task & 3;
        const unsigned char* f = flags + row * 128 + wq * 32;
        unsigned word = 0;
        #pragma unroll
        for (int b = 0; b < 32; b++) word |= ((unsigned)f[b]) << b;
        d_a1bits[(size_t)(m0 + row) * NW1 + (n0 >> 5) + wq] = word;
    }
}

// ------------------------- fc2 / fc3: XNOR-popcount GEMM -----------------
template <int LAYER>
__global__ __launch_bounds__(256) void bgemm_kernel() {
    constexpr int W  = (LAYER == 2) ? NW1 : NW2;     // words along K
    constexpr int KF = (LAYER == 2) ? D1  : D2;      // full K
    constexpr int W4 = W / 4;
    __shared__ __align__(16) unsigned As[64 * W];    // [row][w]
    __shared__ unsigned Bst[W * 33];                 // [w][j], padded

    const unsigned* Ag = (LAYER == 2) ? d_a1bits : d_a2bits;
    const unsigned* Bg = (LAYER == 2) ? d_w2bits : d_w3bits;

    int tid = threadIdx.x;
    int j0 = blockIdx.x * 32, i0 = blockIdx.y * 64;

    for (int i = tid; i < 64 * W4; i += 256) {
        int row = i / W4, w4 = i % W4;
        ((uint4*)As)[row * W4 + w4] = *((const uint4*)(Ag + (size_t)(i0 + row) * W) + w4);
    }
    for (int i = tid; i < 32 * W; i += 256) {
        int j = i / W, w = i % W;
        Bst[w * 33 + j] = Bg[(size_t)(j0 + j) * W + w];
    }
    __syncthreads();

    int warp = tid >> 5, lane = tid & 31;
    int acc[8];
    #pragma unroll
    for (int r = 0; r < 8; r++) acc[r] = 0;

    const unsigned* Arow = As + (warp * 8) * W;
    #pragma unroll 4
    for (int w = 0; w < W; ++w) {
        unsigned b = Bst[w * 33 + lane];
        #pragma unroll
        for (int r = 0; r < 8; r++) acc[r] += __popc(Arow[r * W + w] ^ b);
    }

    int j = j0 + lane;
    if (LAYER == 2) {
        float thr = d_thr2[j], sg = d_sg2[j];
        #pragma unroll
        for (int r = 0; r < 8; r++) {
            float dot = (float)(KF - 2 * acc[r]);
            unsigned word = __ballot_sync(0xffffffffu, sg * (dot - thr) > 0.f);
            if (lane == 0) d_a2bits[(size_t)(i0 + warp * 8 + r) * NW2 + (j0 >> 5)] = word;
        }
    } else {
        float s = d_s3[j], o = d_o3[j];
        #pragma unroll
        for (int r = 0; r < 8; r++) {
            float dot = (float)(KF - 2 * acc[r]);
            float v = fminf(fmaxf(s * dot + o, -1.f), 1.f);
            d_h3c[(size_t)(i0 + warp * 8 + r) * D3 + j] = v;
        }
    }
}

// ------------------------- fc4 + log_softmax -----------------------------
__global__ __launch_bounds__(256) void fc4_kernel(const float* __restrict__ w4,
                                                  const float* __restrict__ b4,
                                                  float* __restrict__ out) {
    __shared__ float ws[D4 * D3];   // 30720 B
    int tid = threadIdx.x;
    for (int i = tid; i < D4 * D3; i += 256) ws[i] = w4[i];
    __syncthreads();

    int warp = tid >> 5, lane = tid & 31;
    int row = blockIdx.x * 8 + warp;
    const float* h = d_h3c + (size_t)row * D3;

    float acc[D4];
    #pragma unroll
    for (int c = 0; c < D4; c++) acc[c] = 0.f;

    #pragma unroll 4
    for (int t = 0; t < D3 / 32; ++t) {
        int k = t * 32 + lane;
        float hv = h[k];
        #pragma unroll
        for (int c = 0; c < D4; c++) acc[c] = fmaf(hv, ws[c * D3 + k], acc[c]);
    }
    #pragma unroll
    for (int c = 0; c < D4; c++) {
        #pragma unroll
        for (int off = 16; off; off >>= 1)
            acc[c] += __shfl_xor_sync(0xffffffffu, acc[c], off);
    }
    if (lane == 0) {
        float l[D4];
        float mx = -1e30f;
        #pragma unroll
        for (int c = 0; c < D4; c++) {
            l[c] = acc[c] + b4[c];
            mx = fmaxf(mx, l[c]);
        }
        float s = 0.f;
        #pragma unroll
        for (int c = 0; c < D4; c++) s += expf(l[c] - mx);
        float lse = mx + logf(s);
        #pragma unroll
        for (int c = 0; c < D4; c++) out[(size_t)row * D4 + c] = l[c] - lse;
    }
}

// ------------------------- launch ----------------------------------------
extern "C" void kernel_launch(void* const* d_in, const int* in_sizes, int n_in,
                              void* d_out, int out_size) {
    const float* x   = (const float*)d_in[0];
    const float* w1  = (const float*)d_in[1];
    const float* b1  = (const float*)d_in[2];
    const float* w2  = (const float*)d_in[3];
    const float* b2  = (const float*)d_in[4];
    const float* w3  = (const float*)d_in[5];
    const float* b3  = (const float*)d_in[6];
    const float* w4  = (const float*)d_in[7];
    const float* b4  = (const float*)d_in[8];
    const float* g1  = (const float*)d_in[9];
    const float* be1 = (const float*)d_in[10];
    const float* m1  = (const float*)d_in[11];
    const float* v1  = (const float*)d_in[12];
    const float* g2  = (const float*)d_in[13];
    const float* be2 = (const float*)d_in[14];
    const float* m2  = (const float*)d_in[15];
    const float* v2  = (const float*)d_in[16];
    const float* g3  = (const float*)d_in[17];
    const float* be3 = (const float*)d_in[18];
    const float* m3  = (const float*)d_in[19];
    const float* v3  = (const float*)d_in[20];

    prep_w1s<<<(D1 * D0 + 255) / 256, 256>>>(w1);
    prep_bits<<<(D2 * NW1 + 255) / 256, 256>>>(w2, w3);
    prep_params<<<(D1 + 255) / 256, 256>>>(b1, g1, be1, m1, v1,
                                           b2, g2, be2, m2, v2,
                                           b3, g3, be3, m3, v3);
    gemm1_kernel<<<dim3(D1 / 128, B_ / 128), 256>>>(x);
    bgemm_kernel<2><<<dim3(D2 / 32, B_ / 64), 256>>>();
    bgemm_kernel<3><<<dim3(D3 / 32, B_ / 64), 256>>>();
    fc4_kernel<<<B_ / 8, 256>>>(w4, b4, (float*)d_out);
}

// round 2
// speedup vs baseline: 1.0003x; 1.0003x over previous
#include <cuda_runtime.h>

#define EPSBN 1e-5f

#define B_  16384
#define D0  784
#define D1  3072
#define D2  1536
#define D3  768
#define D4  10
#define NW1 (D1/32)   // 96 words per row of layer-2 input bits
#define NW2 (D2/32)   // 48 words per row of layer-3 input bits

// ------------------------- static device scratch -------------------------
__device__ float        d_w1s[D0*D1];       // sign(w1) transposed [K][N], float +-1 (or 0)
__device__ unsigned     d_w2bits[D2*NW1];
__device__ unsigned     d_w3bits[D3*NW2];
__device__ unsigned     d_a1bits[B_*NW1];   // sign(bn1) bits
__device__ unsigned     d_a2bits[B_*NW2];   // sign(bn2) bits
__device__ float        d_h3c[B_*D3];       // clip(bn3)
__device__ float        d_thr1[D1], d_sg1[D1];
__device__ float        d_thr2[D2], d_sg2[D2];
__device__ float        d_s3[D3],   d_o3[D3];

// ------------------------- f32x2 helpers (sm_103a FFMA2 path) -------------
__device__ __forceinline__ unsigned long long pack2dup(float a) {
    unsigned long long r;
    asm("mov.b64 %0, {%1, %2};" : "=l"(r) : "f"(a), "f"(a));
    return r;
}
__device__ __forceinline__ void fma2(unsigned long long& d, unsigned long long a, unsigned long long b) {
    asm("fma.rn.f32x2 %0, %1, %2, %0;" : "+l"(d) : "l"(a), "l"(b));
}
__device__ __forceinline__ void unpack2(unsigned long long v, float& x, float& y) {
    asm("mov.b64 {%0, %1}, %2;" : "=f"(x), "=f"(y) : "l"(v));
}

// ------------------------- prep kernels ----------------------------------
__global__ void prep_w1s(const float* __restrict__ w1) {
    int idx = blockIdx.x * 256 + threadIdx.x;
    if (idx >= D1 * D0) return;
    int n = idx / D0, k = idx % D0;
    float w = w1[idx];
    d_w1s[k * D1 + n] = (w > 0.f) ? 1.f : (w < 0.f ? -1.f : 0.f);
}

__global__ void prep_bits(const float* __restrict__ w2, const float* __restrict__ w3) {
    int idx = blockIdx.x * 256 + threadIdx.x;
    if (idx < D2 * NW1) {
        int j = idx / NW1, w = idx % NW1;
        const float* p = w2 + j * D1 + w * 32;
        unsigned word = 0;
        #pragma unroll
        for (int b = 0; b < 32; b++) word |= (p[b] > 0.f) ? (1u << b) : 0u;
        d_w2bits[idx] = word;
    }
    if (idx < D3 * NW2) {
        int j = idx / NW2, w = idx % NW2;
        const float* p = w3 + j * D2 + w * 32;
        unsigned word = 0;
        #pragma unroll
        for (int b = 0; b < 32; b++) word |= (p[b] > 0.f) ? (1u << b) : 0u;
        d_w3bits[idx] = word;
    }
}

__global__ void prep_params(
    const float* __restrict__ b1, const float* __restrict__ g1, const float* __restrict__ be1,
    const float* __restrict__ m1, const float* __restrict__ v1,
    const float* __restrict__ b2, const float* __restrict__ g2, const float* __restrict__ be2,
    const float* __restrict__ m2, const float* __restrict__ v2,
    const float* __restrict__ b3, const float* __restrict__ g3, const float* __restrict__ be3,
    const float* __restrict__ m3, const float* __restrict__ v3)
{
    int j = blockIdx.x * 256 + threadIdx.x;
    if (j < D1) {
        float g = g1[j];
        d_thr1[j] = m1[j] - be1[j] * sqrtf(v1[j] + EPSBN) / g - b1[j];
        d_sg1[j]  = (g > 0.f) ? 1.f : -1.f;
    }
    if (j < D2) {
        float g = g2[j];
        d_thr2[j] = m2[j] - be2[j] * sqrtf(v2[j] + EPSBN) / g - b2[j];
        d_sg2[j]  = (g > 0.f) ? 1.f : -1.f;
    }
    if (j < D3) {
        float g = g3[j];
        float s = g / sqrtf(v3[j] + EPSBN);
        d_s3[j] = s;
        d_o3[j] = (b3[j] - m3[j]) * s + be3[j];
    }
}

// ------------------------- fc1: fp32 GEMM + BN-threshold + bitpack -------
// C[16384,3072] = x[16384,784] * w1s[784,3072]; epilogue: bit = sg*(dot-thr)>0
__global__ __launch_bounds__(256, 2) void gemm1_kernel(const float* __restrict__ x) {
    __shared__ __align__(16) float sm[16 * 132 + 16 * 128];   // As | Bs, 16640 B
    float (*As)[132] = (float(*)[132])sm;                      // [k][m], padded
    float (*Bs)[128] = (float(*)[128])(sm + 16 * 132);         // [k][n]
    unsigned char* flags = (unsigned char*)sm;                 // 16384 B, aliases As/Bs

    int tid = threadIdx.x;
    int tx = tid & 15, ty = tid >> 4;
    int m0 = blockIdx.y * 128, n0 = blockIdx.x * 128;

    unsigned long long acc[8][4];
    #pragma unroll
    for (int r = 0; r < 8; r++)
        #pragma unroll
        for (int c = 0; c < 4; c++) acc[r][c] = 0ull;

    int lr = tid >> 2, lq = tid & 3;       // A loader: row, k-quad
    int bk = tid >> 5, bq = tid & 31;      // B loader: k-row, n-quad
    const float* xA0 = x + (size_t)(m0 + lr)      * D0 + lq * 4;
    const float* xA1 = x + (size_t)(m0 + lr + 64) * D0 + lq * 4;
    const float* pB0 = d_w1s + (size_t)bk       * D1 + n0 + bq * 4;
    const float* pB1 = d_w1s + (size_t)(bk + 8) * D1 + n0 + bq * 4;

    for (int kt = 0; kt < D0; kt += 16) {
        float4 av0 = *(const float4*)(xA0 + kt);
        float4 av1 = *(const float4*)(xA1 + kt);
        float4 bv0 = *(const float4*)(pB0 + (size_t)kt * D1);
        float4 bv1 = *(const float4*)(pB1 + (size_t)kt * D1);
        As[lq * 4 + 0][lr] = av0.x; As[lq * 4 + 1][lr] = av0.y;
        As[lq * 4 + 2][lr] = av0.z; As[lq * 4 + 3][lr] = av0.w;
        As[lq * 4 + 0][lr + 64] = av1.x; As[lq * 4 + 1][lr + 64] = av1.y;
        As[lq * 4 + 2][lr + 64] = av1.z; As[lq * 4 + 3][lr + 64] = av1.w;
        *(float4*)&Bs[bk][bq * 4]     = bv0;
        *(float4*)&Bs[bk + 8][bq * 4] = bv1;
        __syncthreads();

        #pragma unroll
        for (int kk = 0; kk < 16; kk++) {
            float4 a0 = *(const float4*)&As[kk][ty * 8];
            float4 a1 = *(const float4*)&As[kk][ty * 8 + 4];
            double2 q0 = *(const double2*)&Bs[kk][tx * 8];
            double2 q1 = *(const double2*)&Bs[kk][tx * 8 + 4];
            unsigned long long b0 = __double_as_longlong(q0.x);
            unsigned long long b1 = __double_as_longlong(q0.y);
            unsigned long long b2 = __double_as_longlong(q1.x);
            unsigned long long b3 = __double_as_longlong(q1.y);
            float aa[8] = {a0.x, a0.y, a0.z, a0.w, a1.x, a1.y, a1.z, a1.w};
            #pragma unroll
            for (int r = 0; r < 8; r++) {
                unsigned long long ar = pack2dup(aa[r]);
                fma2(acc[r][0], ar, b0);
                fma2(acc[r][1], ar, b1);
                fma2(acc[r][2], ar, b2);
                fma2(acc[r][3], ar, b3);
            }
        }
        __syncthreads();
    }

    // Epilogue: threshold compare -> flags in smem
    float thr[8], sg[8];
    #pragma unroll
    for (int c = 0; c < 8; c++) {
        int n = n0 + tx * 8 + c;
        thr[c] = d_thr1[n];
        sg[c]  = d_sg1[n];
    }
    #pragma unroll
    for (int r = 0; r < 8; r++) {
        #pragma unroll
        for (int c2 = 0; c2 < 4; c2++) {
            float lo, hi;
            unpack2(acc[r][c2], lo, hi);
            int c = c2 * 2;
            flags[(ty * 8 + r) * 128 + tx * 8 + c]     = (sg[c]     * (lo - thr[c])     > 0.f) ? 1 : 0;
            flags[(ty * 8 + r) * 128 + tx * 8 + c + 1] = (sg[c + 1] * (hi - thr[c + 1]) > 0.f) ? 1 : 0;
        }
    }
    __syncthreads();

    // Pack 128x128 flags -> 128 rows x 4 words
    #pragma unroll
    for (int t = 0; t < 2; t++) {
        int task = tid * 2 + t;
        int row = task >> 2, wq = task & 3;
        const unsigned char* f = flags + row * 128 + wq * 32;
        unsigned word = 0;
        #pragma unroll
        for (int b = 0; b < 32; b++) word |= ((unsigned)f[b]) << b;
        d_a1bits[(size_t)(m0 + row) * NW1 + (n0 >> 5) + wq] = word;
    }
}

// ------------------------- fc2 / fc3: XNOR-popcount GEMM -----------------
template <int LAYER>
__global__ __launch_bounds__(256) void bgemm_kernel() {
    constexpr int W  = (LAYER == 2) ? NW1 : NW2;     // words along K
    constexpr int KF = (LAYER == 2) ? D1  : D2;      // full K
    constexpr int W4 = W / 4;
    __shared__ __align__(16) unsigned As[64 * W];    // [row][w]
    __shared__ unsigned Bst[W * 33];                 // [w][j], padded

    const unsigned* Ag = (LAYER == 2) ? d_a1bits : d_a2bits;
    const unsigned* Bg = (LAYER == 2) ? d_w2bits : d_w3bits;

    int tid = threadIdx.x;
    int j0 = blockIdx.x * 32, i0 = blockIdx.y * 64;

    for (int i = tid; i < 64 * W4; i += 256) {
        int row = i / W4, w4 = i % W4;
        ((uint4*)As)[row * W4 + w4] = *((const uint4*)(Ag + (size_t)(i0 + row) * W) + w4);
    }
    for (int i = tid; i < 32 * W; i += 256) {
        int j = i / W, w = i % W;
        Bst[w * 33 + j] = Bg[(size_t)(j0 + j) * W + w];
    }
    __syncthreads();

    int warp = tid >> 5, lane = tid & 31;
    int acc[8];
    #pragma unroll
    for (int r = 0; r < 8; r++) acc[r] = 0;

    const unsigned* Arow = As + (warp * 8) * W;
    #pragma unroll 4
    for (int w = 0; w < W; ++w) {
        unsigned b = Bst[w * 33 + lane];
        #pragma unroll
        for (int r = 0; r < 8; r++) acc[r] += __popc(Arow[r * W + w] ^ b);
    }

    int j = j0 + lane;
    if (LAYER == 2) {
        float thr = d_thr2[j], sg = d_sg2[j];
        #pragma unroll
        for (int r = 0; r < 8; r++) {
            float dot = (float)(KF - 2 * acc[r]);
            unsigned word = __ballot_sync(0xffffffffu, sg * (dot - thr) > 0.f);
            if (lane == 0) d_a2bits[(size_t)(i0 + warp * 8 + r) * NW2 + (j0 >> 5)] = word;
        }
    } else {
        float s = d_s3[j], o = d_o3[j];
        #pragma unroll
        for (int r = 0; r < 8; r++) {
            float dot = (float)(KF - 2 * acc[r]);
            float v = fminf(fmaxf(s * dot + o, -1.f), 1.f);
            d_h3c[(size_t)(i0 + warp * 8 + r) * D3 + j] = v;
        }
    }
}

// ------------------------- fc4 + log_softmax -----------------------------
__global__ __launch_bounds__(256) void fc4_kernel(const float* __restrict__ w4,
                                                  const float* __restrict__ b4,
                                                  float* __restrict__ out) {
    __shared__ float ws[D4 * D3];   // 30720 B
    int tid = threadIdx.x;
    for (int i = tid; i < D4 * D3; i += 256) ws[i] = w4[i];
    __syncthreads();

    int warp = tid >> 5, lane = tid & 31;
    int row = blockIdx.x * 8 + warp;
    const float* h = d_h3c + (size_t)row * D3;

    float acc[D4];
    #pragma unroll
    for (int c = 0; c < D4; c++) acc[c] = 0.f;

    #pragma unroll 4
    for (int t = 0; t < D3 / 32; ++t) {
        int k = t * 32 + lane;
        float hv = h[k];
        #pragma unroll
        for (int c = 0; c < D4; c++) acc[c] = fmaf(hv, ws[c * D3 + k], acc[c]);
    }
    #pragma unroll
    for (int c = 0; c < D4; c++) {
        #pragma unroll
        for (int off = 16; off; off >>= 1)
            acc[c] += __shfl_xor_sync(0xffffffffu, acc[c], off);
    }
    if (lane == 0) {
        float l[D4];
        float mx = -1e30f;
        #pragma unroll
        for (int c = 0; c < D4; c++) {
            l[c] = acc[c] + b4[c];
            mx = fmaxf(mx, l[c]);
        }
        float s = 0.f;
        #pragma unroll
        for (int c = 0; c < D4; c++) s += expf(l[c] - mx);
        float lse = mx + logf(s);
        #pragma unroll
        for (int c = 0; c < D4; c++) out[(size_t)row * D4 + c] = l[c] - lse;
    }
}

// ------------------------- launch ----------------------------------------
extern "C" void kernel_launch(void* const* d_in, const int* in_sizes, int n_in,
                              void* d_out, int out_size) {
    const float* x   = (const float*)d_in[0];
    const float* w1  = (const float*)d_in[1];
    const float* b1  = (const float*)d_in[2];
    const float* w2  = (const float*)d_in[3];
    const float* b2  = (const float*)d_in[4];
    const float* w3  = (const float*)d_in[5];
    const float* b3  = (const float*)d_in[6];
    const float* w4  = (const float*)d_in[7];
    const float* b4  = (const float*)d_in[8];
    const float* g1  = (const float*)d_in[9];
    const float* be1 = (const float*)d_in[10];
    const float* m1  = (const float*)d_in[11];
    const float* v1  = (const float*)d_in[12];
    const float* g2  = (const float*)d_in[13];
    const float* be2 = (const float*)d_in[14];
    const float* m2  = (const float*)d_in[15];
    const float* v2  = (const float*)d_in[16];
    const float* g3  = (const float*)d_in[17];
    const float* be3 = (const float*)d_in[18];
    const float* m3  = (const float*)d_in[19];
    const float* v3  = (const float*)d_in[20];

    prep_w1s<<<(D1 * D0 + 255) / 256, 256>>>(w1);
    prep_bits<<<(D2 * NW1 + 255) / 256, 256>>>(w2, w3);
    prep_params<<<(D1 + 255) / 256, 256>>>(b1, g1, be1, m1, v1,
                                           b2, g2, be2, m2, v2,
                                           b3, g3, be3, m3, v3);
    gemm1_kernel<<<dim3(D1 / 128, B_ / 128), 256>>>(x);
    bgemm_kernel<2><<<dim3(D2 / 32, B_ / 64), 256>>>();
    bgemm_kernel<3><<<dim3(D3 / 32, B_ / 64), 256>>>();
    fc4_kernel<<<B_ / 8, 256>>>(w4, b4, (float*)d_out);
}